// round 8
// baseline (speedup 1.0000x reference)
#include <cuda_runtime.h>
#include <cuda_bf16.h>

#define U 64
#define M 8192
#define D 64
#define CHUNK 512
#define NCHUNK (M / CHUNK)   // 16
#define BLOCK 256
#define NWARP (BLOCK / 32)   // 8
#define SLOTS_PER_WARP (CHUNK / NWARP)   // 64

#define NEG_INF_F __int_as_float(0xff800000)

// Device scratch (no allocations allowed)
__device__ float  g_cmax[U * NCHUNK];
__device__ float  g_csum[U * NCHUNK];
__device__ float4 g_partial4[U * NCHUNK * (D / 4)];

// ---------------------------------------------------------------------------
// Kernel 1 (the only heavy kernel): per (unit, chunk) CTA
//   Phase A: dot products of 512 slots (16 lanes/slot, float4, 2 indep loads)
//   Phase B: mask + temperature, chunk max, e = exp(s - cmax) -> smem AND
//            coalesced to the weights buffer (k2 rescales in place), csum
//   Phase C: stream memories once: e-weighted partial sum + fused copy
// Carries ALL mandatory HBM traffic (keys 134MB + mem 134MB + copy 134MB).
// ---------------------------------------------------------------------------
__global__ void __launch_bounds__(BLOCK)
k_main(const float* __restrict__ q,        // [U, D]
       const float* __restrict__ keys,     // [U, M, D]
       const int*   __restrict__ mask,     // [U, M] (0/1 int32)
       const float* __restrict__ tmpr,     // [U, 1]
       const float* __restrict__ mem,      // [U, M, D]
       float* __restrict__ wbuf,           // [U, M] -> holds e after k1
       float* __restrict__ memout)         // [U, M, D]
{
    __shared__ float  s_e[CHUNK];
    __shared__ float  s_red[NWARP];
    __shared__ float4 s_acc[NWARP][32];

    const int u = blockIdx.y, c = blockIdx.x;
    const int tid = threadIdx.x, lane = tid & 31, warp = tid >> 5;
    const int sub = lane & 15, half = lane >> 4;
    const int m0 = c * CHUNK;

    const float4 q4 = ((const float4*)(q + u * D))[sub];

    // ---- Phase A: raw dots into smem ----
    const int base_slot = warp * SLOTS_PER_WARP;
    #pragma unroll 4
    for (int i = 0; i < SLOTS_PER_WARP / 4; i++) {           // 16 iterations
        const int j0 = base_slot + 4 * i + half;             // slots j0, j0+2
        const size_t r0 = ((size_t)(u * M + m0 + j0))     * D;
        const size_t r1 = ((size_t)(u * M + m0 + j0 + 2)) * D;
        const float4 a = __ldcs((const float4*)(keys + r0) + sub);
        const float4 b = __ldcs((const float4*)(keys + r1) + sub);
        float p0 = a.x * q4.x + a.y * q4.y + a.z * q4.z + a.w * q4.w;
        float p1 = b.x * q4.x + b.y * q4.y + b.z * q4.z + b.w * q4.w;
        #pragma unroll
        for (int o = 1; o < 16; o <<= 1) {
            p0 += __shfl_xor_sync(0xffffffffu, p0, o);
            p1 += __shfl_xor_sync(0xffffffffu, p1, o);
        }
        if (sub == 0) {
            s_e[j0]     = p0;
            s_e[j0 + 2] = p1;
        }
    }
    __syncthreads();

    // ---- Phase B: mask + temperature, cmax, e = exp(s - cmax), csum ----
    const float t = tmpr[u];
    const int j2 = tid * 2;
    const float2 sv = *(const float2*)&s_e[j2];
    const int2  mk = ((const int2*)(mask + u * M + m0))[tid];
    float s0 = ((mk.x != 0) ? -1e9f : sv.x) / t;
    float s1 = ((mk.y != 0) ? -1e9f : sv.y) / t;

    // block max
    float lm = fmaxf(s0, s1);
    #pragma unroll
    for (int o = 16; o > 0; o >>= 1) lm = fmaxf(lm, __shfl_xor_sync(0xffffffffu, lm, o));
    if (lane == 0) s_red[warp] = lm;
    __syncthreads();
    float cmax = s_red[0];
    #pragma unroll
    for (int w = 1; w < NWARP; w++) cmax = fmaxf(cmax, s_red[w]);
    __syncthreads();   // protect s_red reuse

    const float e0 = __expf(s0 - cmax);
    const float e1 = __expf(s1 - cmax);
    // each thread rewrites only its own two slots: no cross-thread hazard
    s_e[j2]     = e0;
    s_e[j2 + 1] = e1;
    // e -> weights buffer (k2 rescales in place; stays L2-resident)
    ((float2*)(wbuf + (size_t)u * M + m0))[tid] = make_float2(e0, e1);

    // block sum of e
    float ls = e0 + e1;
    #pragma unroll
    for (int o = 16; o > 0; o >>= 1) ls += __shfl_xor_sync(0xffffffffu, ls, o);
    if (lane == 0) s_red[warp] = ls;
    __syncthreads();
    if (tid == 0) {
        float sm = 0.0f;
        #pragma unroll
        for (int w = 0; w < NWARP; w++) sm += s_red[w];
        g_cmax[u * NCHUNK + c] = cmax;
        g_csum[u * NCHUNK + c] = sm;
    }
    __syncthreads();   // s_e (e values) visible to all warps

    // ---- Phase C: stream memories once: e-weighted sum + fused copy ----
    float4 acc0 = make_float4(0.0f, 0.0f, 0.0f, 0.0f);
    float4 acc1 = make_float4(0.0f, 0.0f, 0.0f, 0.0f);
    #pragma unroll 4
    for (int i = 0; i < SLOTS_PER_WARP / 4; i++) {
        const int j0 = base_slot + 4 * i + half;
        const size_t r0 = ((size_t)(u * M + m0 + j0))     * D;
        const size_t r1 = ((size_t)(u * M + m0 + j0 + 2)) * D;
        const float4 a = __ldcs((const float4*)(mem + r0) + sub);
        const float4 b = __ldcs((const float4*)(mem + r1) + sub);
        const float wa = s_e[j0];
        const float wb = s_e[j0 + 2];
        acc0.x = fmaf(wa, a.x, acc0.x);
        acc0.y = fmaf(wa, a.y, acc0.y);
        acc0.z = fmaf(wa, a.z, acc0.z);
        acc0.w = fmaf(wa, a.w, acc0.w);
        acc1.x = fmaf(wb, b.x, acc1.x);
        acc1.y = fmaf(wb, b.y, acc1.y);
        acc1.z = fmaf(wb, b.z, acc1.z);
        acc1.w = fmaf(wb, b.w, acc1.w);
        __stcs((float4*)(memout + r0) + sub, a);             // fused copy
        __stcs((float4*)(memout + r1) + sub, b);
    }
    acc0.x += acc1.x; acc0.y += acc1.y; acc0.z += acc1.z; acc0.w += acc1.w;
    s_acc[warp][lane] = acc0;
    __syncthreads();

    if (tid < 16) {
        float4 tsum = make_float4(0.0f, 0.0f, 0.0f, 0.0f);
        #pragma unroll
        for (int w = 0; w < NWARP; w++) {
            #pragma unroll
            for (int h = 0; h < 2; h++) {
                const float4 v = s_acc[w][h * 16 + tid];
                tsum.x += v.x; tsum.y += v.y; tsum.z += v.z; tsum.w += v.w;
            }
        }
        g_partial4[(u * NCHUNK + c) * (D / 4) + tid] = tsum;
    }
}

// ---------------------------------------------------------------------------
// Kernel 2 (small): flash recombine.
//   weights[u,m] = e[u,m] * exp(cmax_c - gmax) / gsum   (in place, L2-hot)
//   block c==0 additionally reduces the 16 chunk partials -> outputs.
// grid (NCHUNK, U), block 256.
// ---------------------------------------------------------------------------
__global__ void __launch_bounds__(BLOCK)
k_fin(float* __restrict__ wbuf,            // [U, M] (e on entry, weights on exit)
      float* __restrict__ outp)            // [U, D]
{
    const int u = blockIdx.y, c = blockIdx.x;
    const int tid = threadIdx.x;
    const int m0 = c * CHUNK;

    float gmax = NEG_INF_F;
    #pragma unroll
    for (int j = 0; j < NCHUNK; j++) gmax = fmaxf(gmax, g_cmax[u * NCHUNK + j]);
    float gsum = 0.0f;
    #pragma unroll
    for (int j = 0; j < NCHUNK; j++)
        gsum += g_csum[u * NCHUNK + j] * __expf(g_cmax[u * NCHUNK + j] - gmax);
    const float inv = 1.0f / gsum;
    const float scale_c = __expf(g_cmax[u * NCHUNK + c] - gmax) * inv;

    const float2 e2 = ((const float2*)(wbuf + (size_t)u * M + m0))[tid];
    __stcs((float2*)(wbuf + (size_t)u * M + m0) + tid,
           make_float2(e2.x * scale_c, e2.y * scale_c));

    // outputs: one block per unit does the 16-chunk partial reduction
    if (c == 0 && tid < D) {
        const float* gp = (const float*)g_partial4;
        float s = 0.0f;
        #pragma unroll
        for (int j = 0; j < NCHUNK; j++) {
            const float sc = __expf(g_cmax[u * NCHUNK + j] - gmax) * inv;
            s = fmaf(gp[(u * NCHUNK + j) * D + tid], sc, s);
        }
        outp[u * D + tid] = s;
    }
}

extern "C" void kernel_launch(void* const* d_in, const int* in_sizes, int n_in,
                              void* d_out, int out_size)
{
    const float* attention  = (const float*)d_in[0];  // [U, D]
    const float* attentions = (const float*)d_in[1];  // [U, M, D]
    const float* memories   = (const float*)d_in[2];  // [U, M, D]
    const float* tmpr       = (const float*)d_in[3];  // [U, 1]
    const int*   mask       = (const int*)  d_in[4];  // [U, M]

    float* out          = (float*)d_out;
    float* out_outputs  = out;                        // [U, D]
    float* out_weights  = out + U * D;                // [U, M]
    float* out_memories = out + U * D + U * M;        // [U, M, D]

    dim3 grid(NCHUNK, U);
    k_main<<<grid, BLOCK>>>(attention, attentions, mask, tmpr, memories,
                            out_weights, out_memories);
    k_fin<<<grid, BLOCK>>>(out_weights, out_outputs);
}

// round 9
// speedup vs baseline: 1.0257x; 1.0257x over previous
#include <cuda_runtime.h>
#include <cuda_bf16.h>

#define U 64
#define M 8192
#define D 64
#define CHUNK 512
#define NCHUNK (M / CHUNK)   // 16
#define BLOCK 256
#define NWARP (BLOCK / 32)   // 8
#define SLOTS_PER_WARP (CHUNK / NWARP)   // 64

#define NEG_INF_F __int_as_float(0xff800000)

// Device scratch (no allocations allowed)
__device__ float  g_cmax[U * NCHUNK];
__device__ float  g_csum[U * NCHUNK];
__device__ float4 g_partial4[U * NCHUNK * (D / 4)];
__device__ int    g_cnt[U];          // zero-init; self-resetting each run

// ---------------------------------------------------------------------------
// Kernel 1: scores + per-chunk softmax stats. (identical to the 76.1us R7)
// grid (NCHUNK, U), block 256.
// ---------------------------------------------------------------------------
__global__ void __launch_bounds__(BLOCK)
k_scores(const float* __restrict__ q,      // [U, D]
         const float* __restrict__ keys,   // [U, M, D]
         const int*   __restrict__ mask,   // [U, M] (0/1 int32)
         const float* __restrict__ tmpr,   // [U, 1]
         float* __restrict__ scores)       // [U, M]
{
    __shared__ float s_s[CHUNK];
    __shared__ float s_red[NWARP];

    const int u = blockIdx.y, c = blockIdx.x;
    const int tid = threadIdx.x, lane = tid & 31, warp = tid >> 5;
    const int sub = lane & 15, half = lane >> 4;
    const int m0 = c * CHUNK;

    const float4 q4 = ((const float4*)(q + u * D))[sub];

    const int base_slot = warp * SLOTS_PER_WARP;
    #pragma unroll 4
    for (int i = 0; i < SLOTS_PER_WARP / 4; i++) {           // 16 iterations
        const int j0 = base_slot + 4 * i + half;             // slots j0, j0+2
        const size_t r0 = ((size_t)(u * M + m0 + j0))     * D;
        const size_t r1 = ((size_t)(u * M + m0 + j0 + 2)) * D;
        const float4 a = __ldcs((const float4*)(keys + r0) + sub);
        const float4 b = __ldcs((const float4*)(keys + r1) + sub);
        float p0 = a.x * q4.x + a.y * q4.y + a.z * q4.z + a.w * q4.w;
        float p1 = b.x * q4.x + b.y * q4.y + b.z * q4.z + b.w * q4.w;
        #pragma unroll
        for (int o = 1; o < 16; o <<= 1) {
            p0 += __shfl_xor_sync(0xffffffffu, p0, o);
            p1 += __shfl_xor_sync(0xffffffffu, p1, o);
        }
        if (sub == 0) {
            s_s[j0]     = p0;
            s_s[j0 + 2] = p1;
        }
    }
    __syncthreads();

    const float t = tmpr[u];
    const int j2 = tid * 2;
    const float2 sv = *(const float2*)&s_s[j2];
    const int2  mk = ((const int2*)(mask + u * M + m0))[tid];
    float s0 = ((mk.x != 0) ? -1e9f : sv.x) / t;
    float s1 = ((mk.y != 0) ? -1e9f : sv.y) / t;
    ((float2*)(scores + (size_t)u * M + m0))[tid] = make_float2(s0, s1);

    float lm = fmaxf(s0, s1);
    #pragma unroll
    for (int o = 16; o > 0; o >>= 1) lm = fmaxf(lm, __shfl_xor_sync(0xffffffffu, lm, o));
    if (lane == 0) s_red[warp] = lm;
    __syncthreads();
    float cmax = s_red[0];
    #pragma unroll
    for (int w = 1; w < NWARP; w++) cmax = fmaxf(cmax, s_red[w]);
    __syncthreads();

    float ls = __expf(s0 - cmax) + __expf(s1 - cmax);
    #pragma unroll
    for (int o = 16; o > 0; o >>= 1) ls += __shfl_xor_sync(0xffffffffu, ls, o);
    if (lane == 0) s_red[warp] = ls;
    __syncthreads();
    if (tid == 0) {
        float sm = 0.0f;
        #pragma unroll
        for (int w = 0; w < NWARP; w++) sm += s_red[w];
        g_cmax[u * NCHUNK + c] = cmax;
        g_csum[u * NCHUNK + c] = sm;
    }
}

// ---------------------------------------------------------------------------
// Kernel 2: recombine -> weights, weighted memory sum + fused memories copy,
// and final outputs reduction by the LAST CTA per unit (completion counter,
// fixed-order sum => deterministic; counter self-resets for graph replay).
// grid (NCHUNK, U), block 256.
// ---------------------------------------------------------------------------
__global__ void __launch_bounds__(BLOCK)
k_out(const float* __restrict__ mem,       // [U, M, D]
      float* __restrict__ weights,         // [U, M] (scores on entry)
      float* __restrict__ memout,          // [U, M, D]
      float* __restrict__ outp)            // [U, D]
{
    __shared__ float  s_w[CHUNK];
    __shared__ float4 s_acc[NWARP][32];
    __shared__ int    s_last;

    const int u = blockIdx.y, c = blockIdx.x;
    const int tid = threadIdx.x, lane = tid & 31, warp = tid >> 5;
    const int sub = lane & 15, half = lane >> 4;
    const int m0 = c * CHUNK;

    // ---- global softmax stats (flash recombine, broadcast loads) ----
    float gmax = NEG_INF_F;
    #pragma unroll
    for (int j = 0; j < NCHUNK; j++) gmax = fmaxf(gmax, g_cmax[u * NCHUNK + j]);
    float gsum = 0.0f;
    #pragma unroll
    for (int j = 0; j < NCHUNK; j++)
        gsum += g_csum[u * NCHUNK + j] * __expf(g_cmax[u * NCHUNK + j] - gmax);
    const float inv = 1.0f / gsum;

    // ---- Phase 1: chunk weights, coalesced (scores likely L2-hot) ----
    const int j2 = tid * 2;
    const float2 sv = ((const float2*)(weights + (size_t)u * M + m0))[tid];
    const float w0 = __expf(sv.x - gmax) * inv;
    const float w1 = __expf(sv.y - gmax) * inv;
    s_w[j2]     = w0;
    s_w[j2 + 1] = w1;
    __stcs((float2*)(weights + (size_t)u * M + m0) + tid, make_float2(w0, w1));
    __syncthreads();

    // ---- Phase 2: stream memories once: weighted sum + fused copy ----
    float4 acc0 = make_float4(0.0f, 0.0f, 0.0f, 0.0f);
    float4 acc1 = make_float4(0.0f, 0.0f, 0.0f, 0.0f);
    const int base_slot = warp * SLOTS_PER_WARP;
    #pragma unroll 4
    for (int i = 0; i < SLOTS_PER_WARP / 4; i++) {
        const int j0 = base_slot + 4 * i + half;
        const size_t r0 = ((size_t)(u * M + m0 + j0))     * D;
        const size_t r1 = ((size_t)(u * M + m0 + j0 + 2)) * D;
        const float4 a = __ldcs((const float4*)(mem + r0) + sub);
        const float4 b = __ldcs((const float4*)(mem + r1) + sub);
        const float wa = s_w[j0];
        const float wb = s_w[j0 + 2];
        acc0.x = fmaf(wa, a.x, acc0.x);
        acc0.y = fmaf(wa, a.y, acc0.y);
        acc0.z = fmaf(wa, a.z, acc0.z);
        acc0.w = fmaf(wa, a.w, acc0.w);
        acc1.x = fmaf(wb, b.x, acc1.x);
        acc1.y = fmaf(wb, b.y, acc1.y);
        acc1.z = fmaf(wb, b.z, acc1.z);
        acc1.w = fmaf(wb, b.w, acc1.w);
        __stcs((float4*)(memout + r0) + sub, a);             // fused copy
        __stcs((float4*)(memout + r1) + sub, b);
    }
    acc0.x += acc1.x; acc0.y += acc1.y; acc0.z += acc1.z; acc0.w += acc1.w;
    s_acc[warp][lane] = acc0;
    __syncthreads();

    // ---- Phase 3: per-chunk partial (final-scaled) to global scratch ----
    if (tid < 16) {
        float4 tsum = make_float4(0.0f, 0.0f, 0.0f, 0.0f);
        #pragma unroll
        for (int w = 0; w < NWARP; w++) {
            #pragma unroll
            for (int h = 0; h < 2; h++) {
                const float4 v = s_acc[w][h * 16 + tid];
                tsum.x += v.x; tsum.y += v.y; tsum.z += v.z; tsum.w += v.w;
            }
        }
        g_partial4[(u * NCHUNK + c) * (D / 4) + tid] = tsum;
    }

    // ---- Phase 4: last CTA of this unit reduces the 16 partials ----
    __threadfence();                       // partials visible before counter
    __syncthreads();                       // all warps' partials written
    if (tid == 0) {
        const int n = atomicAdd(&g_cnt[u], 1);
        s_last = (n == NCHUNK - 1);
    }
    __syncthreads();
    if (s_last) {
        if (tid < 16) {
            float4 tsum = make_float4(0.0f, 0.0f, 0.0f, 0.0f);
            #pragma unroll
            for (int j = 0; j < NCHUNK; j++) {   // fixed order -> deterministic
                const float4 v = g_partial4[(u * NCHUNK + j) * (D / 4) + tid];
                tsum.x += v.x; tsum.y += v.y; tsum.z += v.z; tsum.w += v.w;
            }
            ((float4*)(outp + u * D))[tid] = tsum;
        }
        if (tid == 0) g_cnt[u] = 0;        // reset for next graph replay
    }
}

extern "C" void kernel_launch(void* const* d_in, const int* in_sizes, int n_in,
                              void* d_out, int out_size)
{
    const float* attention  = (const float*)d_in[0];  // [U, D]
    const float* attentions = (const float*)d_in[1];  // [U, M, D]
    const float* memories   = (const float*)d_in[2];  // [U, M, D]
    const float* tmpr       = (const float*)d_in[3];  // [U, 1]
    const int*   mask       = (const int*)  d_in[4];  // [U, M]

    float* out          = (float*)d_out;
    float* out_outputs  = out;                        // [U, D]
    float* out_weights  = out + U * D;                // [U, M]
    float* out_memories = out + U * D + U * M;        // [U, M, D]

    dim3 grid(NCHUNK, U);
    k_scores<<<grid, BLOCK>>>(attention, attentions, mask, tmpr, out_weights);
    k_out<<<grid, BLOCK>>>(memories, out_weights, out_memories, out_outputs);
}

// round 10
// speedup vs baseline: 1.0595x; 1.0329x over previous
#include <cuda_runtime.h>
#include <cuda_bf16.h>

#define U 64
#define M 8192
#define D 64
#define CHUNK 512
#define NCHUNK (M / CHUNK)   // 16
#define BLOCK 256
#define NWARP (BLOCK / 32)   // 8
#define SLOTS_PER_WARP (CHUNK / NWARP)   // 64

#define NEG_INF_F __int_as_float(0xff800000)

// Device scratch (no allocations allowed)
__device__ float g_cmax[U * NCHUNK];
__device__ float g_csum[U * NCHUNK];

// ---------------------------------------------------------------------------
// Kernel 1: scores + per-chunk softmax stats (identical hot path to R7 76.1us)
// + block c==0 zeroes this unit's outputs (k_out accumulates atomically).
// grid (NCHUNK, U), block 256.
// ---------------------------------------------------------------------------
__global__ void __launch_bounds__(BLOCK)
k_scores(const float* __restrict__ q,      // [U, D]
         const float* __restrict__ keys,   // [U, M, D]
         const int*   __restrict__ mask,   // [U, M] (0/1 int32)
         const float* __restrict__ tmpr,   // [U, 1]
         float* __restrict__ scores,       // [U, M]
         float* __restrict__ outp)         // [U, D] -> zeroed here
{
    __shared__ float s_s[CHUNK];
    __shared__ float s_red[NWARP];

    const int u = blockIdx.y, c = blockIdx.x;
    const int tid = threadIdx.x, lane = tid & 31, warp = tid >> 5;
    const int sub = lane & 15, half = lane >> 4;
    const int m0 = c * CHUNK;

    if (c == 0 && tid < D / 4)
        ((float4*)(outp + u * D))[tid] = make_float4(0.0f, 0.0f, 0.0f, 0.0f);

    const float4 q4 = ((const float4*)(q + u * D))[sub];

    const int base_slot = warp * SLOTS_PER_WARP;
    #pragma unroll 4
    for (int i = 0; i < SLOTS_PER_WARP / 4; i++) {           // 16 iterations
        const int j0 = base_slot + 4 * i + half;             // slots j0, j0+2
        const size_t r0 = ((size_t)(u * M + m0 + j0))     * D;
        const size_t r1 = ((size_t)(u * M + m0 + j0 + 2)) * D;
        const float4 a = __ldcs((const float4*)(keys + r0) + sub);
        const float4 b = __ldcs((const float4*)(keys + r1) + sub);
        float p0 = a.x * q4.x + a.y * q4.y + a.z * q4.z + a.w * q4.w;
        float p1 = b.x * q4.x + b.y * q4.y + b.z * q4.z + b.w * q4.w;
        #pragma unroll
        for (int o = 1; o < 16; o <<= 1) {
            p0 += __shfl_xor_sync(0xffffffffu, p0, o);
            p1 += __shfl_xor_sync(0xffffffffu, p1, o);
        }
        if (sub == 0) {
            s_s[j0]     = p0;
            s_s[j0 + 2] = p1;
        }
    }
    __syncthreads();

    const float t = tmpr[u];
    const int j2 = tid * 2;
    const float2 sv = *(const float2*)&s_s[j2];
    const int2  mk = ((const int2*)(mask + u * M + m0))[tid];
    float s0 = ((mk.x != 0) ? -1e9f : sv.x) / t;
    float s1 = ((mk.y != 0) ? -1e9f : sv.y) / t;
    ((float2*)(scores + (size_t)u * M + m0))[tid] = make_float2(s0, s1);

    float lm = fmaxf(s0, s1);
    #pragma unroll
    for (int o = 16; o > 0; o >>= 1) lm = fmaxf(lm, __shfl_xor_sync(0xffffffffu, lm, o));
    if (lane == 0) s_red[warp] = lm;
    __syncthreads();
    float cmax = s_red[0];
    #pragma unroll
    for (int w = 1; w < NWARP; w++) cmax = fmaxf(cmax, s_red[w]);
    __syncthreads();

    float ls = __expf(s0 - cmax) + __expf(s1 - cmax);
    #pragma unroll
    for (int o = 16; o > 0; o >>= 1) ls += __shfl_xor_sync(0xffffffffu, ls, o);
    if (lane == 0) s_red[warp] = ls;
    __syncthreads();
    if (tid == 0) {
        float sm = 0.0f;
        #pragma unroll
        for (int w = 0; w < NWARP; w++) sm += s_red[w];
        g_cmax[u * NCHUNK + c] = cmax;
        g_csum[u * NCHUNK + c] = sm;
    }
}

// ---------------------------------------------------------------------------
// Kernel 2: recombine -> weights, weighted memory sum + fused memories copy.
// Per-chunk partial goes straight into outputs via atomicAdd (16 thr x 4
// floats per CTA; no fence, no counter, no third kernel).
// grid (NCHUNK, U), block 256.
// ---------------------------------------------------------------------------
__global__ void __launch_bounds__(BLOCK)
k_out(const float* __restrict__ mem,       // [U, M, D]
      float* __restrict__ weights,         // [U, M] (scores on entry)
      float* __restrict__ memout,          // [U, M, D]
      float* __restrict__ outp)            // [U, D] (zeroed by k_scores)
{
    __shared__ float  s_w[CHUNK];
    __shared__ float4 s_acc[NWARP][32];

    const int u = blockIdx.y, c = blockIdx.x;
    const int tid = threadIdx.x, lane = tid & 31, warp = tid >> 5;
    const int sub = lane & 15, half = lane >> 4;
    const int m0 = c * CHUNK;

    // ---- global softmax stats (flash recombine, broadcast loads) ----
    float gmax = NEG_INF_F;
    #pragma unroll
    for (int j = 0; j < NCHUNK; j++) gmax = fmaxf(gmax, g_cmax[u * NCHUNK + j]);
    float gsum = 0.0f;
    #pragma unroll
    for (int j = 0; j < NCHUNK; j++)
        gsum += g_csum[u * NCHUNK + j] * __expf(g_cmax[u * NCHUNK + j] - gmax);
    const float inv = 1.0f / gsum;

    // ---- Phase 1: chunk weights, coalesced (scores likely L2-hot) ----
    const int j2 = tid * 2;
    const float2 sv = ((const float2*)(weights + (size_t)u * M + m0))[tid];
    const float w0 = __expf(sv.x - gmax) * inv;
    const float w1 = __expf(sv.y - gmax) * inv;
    s_w[j2]     = w0;
    s_w[j2 + 1] = w1;
    __stcs((float2*)(weights + (size_t)u * M + m0) + tid, make_float2(w0, w1));
    __syncthreads();

    // ---- Phase 2: stream memories once: weighted sum + fused copy ----
    float4 acc0 = make_float4(0.0f, 0.0f, 0.0f, 0.0f);
    float4 acc1 = make_float4(0.0f, 0.0f, 0.0f, 0.0f);
    const int base_slot = warp * SLOTS_PER_WARP;
    #pragma unroll 4
    for (int i = 0; i < SLOTS_PER_WARP / 4; i++) {
        const int j0 = base_slot + 4 * i + half;
        const size_t r0 = ((size_t)(u * M + m0 + j0))     * D;
        const size_t r1 = ((size_t)(u * M + m0 + j0 + 2)) * D;
        const float4 a = __ldcs((const float4*)(mem + r0) + sub);
        const float4 b = __ldcs((const float4*)(mem + r1) + sub);
        const float wa = s_w[j0];
        const float wb = s_w[j0 + 2];
        acc0.x = fmaf(wa, a.x, acc0.x);
        acc0.y = fmaf(wa, a.y, acc0.y);
        acc0.z = fmaf(wa, a.z, acc0.z);
        acc0.w = fmaf(wa, a.w, acc0.w);
        acc1.x = fmaf(wb, b.x, acc1.x);
        acc1.y = fmaf(wb, b.y, acc1.y);
        acc1.z = fmaf(wb, b.z, acc1.z);
        acc1.w = fmaf(wb, b.w, acc1.w);
        __stcs((float4*)(memout + r0) + sub, a);             // fused copy
        __stcs((float4*)(memout + r1) + sub, b);
    }
    acc0.x += acc1.x; acc0.y += acc1.y; acc0.z += acc1.z; acc0.w += acc1.w;
    s_acc[warp][lane] = acc0;
    __syncthreads();

    // ---- Phase 3: chunk partial -> outputs via atomicAdd (no 3rd kernel) ----
    if (tid < 16) {
        float4 tsum = make_float4(0.0f, 0.0f, 0.0f, 0.0f);
        #pragma unroll
        for (int w = 0; w < NWARP; w++) {
            #pragma unroll
            for (int h = 0; h < 2; h++) {
                const float4 v = s_acc[w][h * 16 + tid];
                tsum.x += v.x; tsum.y += v.y; tsum.z += v.z; tsum.w += v.w;
            }
        }
        float* dst = outp + u * D + tid * 4;
        atomicAdd(dst + 0, tsum.x);
        atomicAdd(dst + 1, tsum.y);
        atomicAdd(dst + 2, tsum.z);
        atomicAdd(dst + 3, tsum.w);
    }
}

extern "C" void kernel_launch(void* const* d_in, const int* in_sizes, int n_in,
                              void* d_out, int out_size)
{
    const float* attention  = (const float*)d_in[0];  // [U, D]
    const float* attentions = (const float*)d_in[1];  // [U, M, D]
    const float* memories   = (const float*)d_in[2];  // [U, M, D]
    const float* tmpr       = (const float*)d_in[3];  // [U, 1]
    const int*   mask       = (const int*)  d_in[4];  // [U, M]

    float* out          = (float*)d_out;
    float* out_outputs  = out;                        // [U, D]
    float* out_weights  = out + U * D;                // [U, M]
    float* out_memories = out + U * D + U * M;        // [U, M, D]

    dim3 grid(NCHUNK, U);
    k_scores<<<grid, BLOCK>>>(attention, attentions, mask, tmpr,
                              out_weights, out_outputs);
    k_out<<<grid, BLOCK>>>(memories, out_weights, out_memories, out_outputs);
}